// round 6
// baseline (speedup 1.0000x reference)
#include <cuda_runtime.h>
#include <cuda_fp16.h>
#include <math_constants.h>
#include <cstdint>

// ---------------------------------------------------------------------------
// DIMES dense encoder, B=16, N=200, U=64, L=3
// Full-recompute scheme: NO edge tensor in DRAM. Every edge kernel rebuilds
// w0 from adj (2.5MB) and replays the layer chain with fp16 tensor-core GEMMs.
// ---------------------------------------------------------------------------

constexpr int B_ = 16, N_ = 200, M_ = 199, U_ = 64;
constexpr int BN_ = B_ * N_;                     // 3200
constexpr long long E_ = (long long)BN_ * M_;    // 636800 edge rows
constexpr float EPS_ = 1e-5f;

__device__ __align__(16) float g_h[BN_ * U_];
__device__ __align__(16) float g_x[3][4][BN_ * U_];   // per-layer x1..x4
__device__ unsigned g_pooled_u[BN_ * U_];             // order-encoded max
__device__ double g_estats[2 * U_];
__device__ double g_hstats[2 * U_];
__device__ __align__(16) float g_ecoef[3][2][U_];     // per-layer scale/shift
__device__ __align__(16) float g_hcoef[2 * U_];

__device__ __forceinline__ float lrelu(float v) { return v >= 0.f ? v : 0.01f * v; }

// order-preserving float<->uint for atomicMax (0u acts as -inf)
__device__ __forceinline__ unsigned enc_f(float f) {
    unsigned u = __float_as_uint(f);
    return u ^ ((u & 0x80000000u) ? 0xffffffffu : 0x80000000u);
}
__device__ __forceinline__ float dec_f(unsigned k) {
    return __uint_as_float((k & 0x80000000u) ? (k ^ 0x80000000u) : ~k);
}

__device__ __forceinline__ void mma16(float c[4], unsigned a0, unsigned a1,
                                      unsigned a2, unsigned a3,
                                      unsigned b0, unsigned b1) {
    asm volatile(
        "mma.sync.aligned.m16n8k16.row.col.f32.f16.f16.f32 "
        "{%0,%1,%2,%3}, {%4,%5,%6,%7}, {%8,%9}, {%0,%1,%2,%3};"
        : "+f"(c[0]), "+f"(c[1]), "+f"(c[2]), "+f"(c[3])
        : "r"(a0), "r"(a1), "r"(a2), "r"(a3), "r"(b0), "r"(b1));
}

// C(64x64,f32 frags) = W(64x64 fp16 smem, row stride 72) @ E^T(fp16 smem [col][k], stride 72)
__device__ __forceinline__ void do_gemm16(const __half* __restrict__ W,
                                          const __half* __restrict__ ET,
                                          float cf[4][4], int la, int ncol0, int tig) {
    const int grp = (threadIdx.x & 31) >> 2;
#pragma unroll
    for (int nt = 0; nt < 4; nt++) { cf[nt][0]=0.f; cf[nt][1]=0.f; cf[nt][2]=0.f; cf[nt][3]=0.f; }
#pragma unroll
    for (int k0 = 0; k0 < 64; k0 += 16) {
        unsigned a0 = *(const unsigned*)&W[la * 72 + k0 + 2 * tig];
        unsigned a1 = *(const unsigned*)&W[(la + 8) * 72 + k0 + 2 * tig];
        unsigned a2 = *(const unsigned*)&W[la * 72 + k0 + 8 + 2 * tig];
        unsigned a3 = *(const unsigned*)&W[(la + 8) * 72 + k0 + 8 + 2 * tig];
#pragma unroll
        for (int nt = 0; nt < 4; nt++) {
            int col = ncol0 + nt * 8 + grp;
            unsigned b0 = *(const unsigned*)&ET[col * 72 + k0 + 2 * tig];
            unsigned b1 = *(const unsigned*)&ET[col * 72 + k0 + 8 + 2 * tig];
            mma16(cf[nt], a0, a1, a2, a3, b0, b1);
        }
    }
}

// ---------------------------------------------------------------------------
// Edge kernel: grid = BN_*4, one block per (bn, 64-row tile), 256 threads.
// Rebuild w0 from adj, run NP GEMM passes; apply bn_l between passes;
// final pass: STATS (+POOLED) or LAST (apply+project).
// ---------------------------------------------------------------------------
template<int NP, bool POOLED, bool STATS, bool LAST>
__global__ void __launch_bounds__(256) k_edge(
    const float* __restrict__ adj, const float* __restrict__ ew0, const float* __restrict__ eb0,
    const float* __restrict__ Ew,  const float* __restrict__ Eb,
    const float* __restrict__ e1w, const float* __restrict__ e1b,
    float* __restrict__ out)
{
    __shared__ __half W_sh[64 * 72];
    __shared__ __half eT[NP * 64 * 72];
    __shared__ float zc_sh[NP][64];
    __shared__ float s_sh[NP][64], sf_sh[NP][64];
    __shared__ float adj_sh[72];
    __shared__ float ssum[64], ssq[64];
    __shared__ unsigned pool_sh[64];
    __shared__ float e1w_sh[64];
    __shared__ float sred[128];

    const int bid = blockIdx.x;
    const int bn = bid >> 2, tile = bid & 3;
    const int m0 = tile * 64;
    const int n = bn % N_, b = bn / N_;
    const int t = threadIdx.x;
    const int lane = t & 31, wp = t >> 5, grp = lane >> 2, tig = lane & 3;
    const int la = (wp & 3) * 16 + grp;
    const int lb = la + 8;
    const int ncol0 = (wp >> 2) * 32;
    const int m_a = m0 + la, m_b = m0 + lb;
    const bool va = m_a < M_, vb = m_b < M_;
    const int dst_a = m_a + (m_a >= n), dst_b = m_b + (m_b >= n);

    // constants / small arrays
    if (t < 64) {
#pragma unroll
        for (int l = 0; l < NP; l++)
            zc_sh[l][t] = __ldg(&Eb[l * 64 + t]) + g_x[l][2][bn * U_ + t];
#pragma unroll
        for (int l = 0; l < NP; l++) {
            if (l < NP - 1 || LAST) {
                s_sh[l][t]  = g_ecoef[l][0][t];
                sf_sh[l][t] = g_ecoef[l][1][t];
            }
        }
        if (STATS) { ssum[t] = 0.f; ssq[t] = 0.f; }
        if (POOLED) pool_sh[t] = 0u;
        if (LAST) e1w_sh[t] = __ldg(&e1w[t]);
    }
    if (t < 72) {
        int a = m0 + t;
        adj_sh[t] = __ldg(&adj[(size_t)bn * N_ + min(a, N_ - 1)]);
    }

    // E matrices, transposed to [col][k], fp16
#pragma unroll
    for (int l = 0; l < NP; l++) {
        for (int idx = t; idx < 2048; idx += 256) {
            int u = idx >> 5, kk = (idx & 31) * 2;
            float e0 = __ldg(&Ew[l * 4096 + kk * 64 + u]);
            float e1 = __ldg(&Ew[l * 4096 + (kk + 1) * 64 + u]);
            *(__half2*)&eT[l * 4608 + u * 72 + kk] = __floats2half2_rn(e0, e1);
        }
    }
    __syncthreads();

    // build w0 tile (fp16) from adj
    for (int idx = t; idx < 2048; idx += 256) {
        int rr = idx >> 5, cu = (idx & 31) * 2;
        int m = m0 + rr;
        float a = (m < M_) ? adj_sh[rr + (m >= n)] : 0.f;
        float wa = lrelu(fmaf(a, __ldg(&ew0[cu]),     __ldg(&eb0[cu])));
        float wb = lrelu(fmaf(a, __ldg(&ew0[cu + 1]), __ldg(&eb0[cu + 1])));
        *(__half2*)&W_sh[rr * 72 + cu] = __floats2half2_rn(wa, wb);
    }
    __syncthreads();

    float cf[4][4];
#pragma unroll
    for (int l = 0; l < NP; l++) {
        // prefetch x4_l gathers (and x2 on the final pooled pass)
        const float* x4l = &g_x[l][3][(size_t)b * N_ * U_];
        float2 x4a[4], x4b[4], x2a[4], x2b[4];
#pragma unroll
        for (int nt = 0; nt < 4; nt++) {
            int cc = ncol0 + nt * 8 + 2 * tig;
            x4a[nt] = va ? __ldg((const float2*)&x4l[dst_a * U_ + cc]) : make_float2(0.f, 0.f);
            x4b[nt] = vb ? __ldg((const float2*)&x4l[dst_b * U_ + cc]) : make_float2(0.f, 0.f);
        }
        if (POOLED && l == NP - 1) {
            const float* x2l = &g_x[l][1][(size_t)b * N_ * U_];
#pragma unroll
            for (int nt = 0; nt < 4; nt++) {
                int cc = ncol0 + nt * 8 + 2 * tig;
                x2a[nt] = va ? __ldg((const float2*)&x2l[dst_a * U_ + cc]) : make_float2(0.f, 0.f);
                x2b[nt] = vb ? __ldg((const float2*)&x2l[dst_b * U_ + cc]) : make_float2(0.f, 0.f);
            }
        }

        do_gemm16(W_sh, eT + l * 4608, cf, la, ncol0, tig);

        if (l < NP - 1) {
            // apply bn_l residual: w_{l+1} = w_l + lrelu(bn(z_l))
            __syncthreads();   // all GEMM reads of W_sh done
#pragma unroll
            for (int nt = 0; nt < 4; nt++) {
                int cc = ncol0 + nt * 8 + 2 * tig;
                float zk0 = zc_sh[l][cc], zk1 = zc_sh[l][cc + 1];
                float sc0 = s_sh[l][cc], sc1 = s_sh[l][cc + 1];
                float f0 = sf_sh[l][cc], f1 = sf_sh[l][cc + 1];
                if (va) {
                    float2 wv = __half22float2(*(__half2*)&W_sh[la * 72 + cc]);
                    float z0 = cf[nt][0] + zk0 + x4a[nt].x;
                    float z1 = cf[nt][1] + zk1 + x4a[nt].y;
                    wv.x += lrelu(fmaf(z0, sc0, f0));
                    wv.y += lrelu(fmaf(z1, sc1, f1));
                    *(__half2*)&W_sh[la * 72 + cc] = __floats2half2_rn(wv.x, wv.y);
                }
                if (vb) {
                    float2 wv = __half22float2(*(__half2*)&W_sh[lb * 72 + cc]);
                    float z0 = cf[nt][2] + zk0 + x4b[nt].x;
                    float z1 = cf[nt][3] + zk1 + x4b[nt].y;
                    wv.x += lrelu(fmaf(z0, sc0, f0));
                    wv.y += lrelu(fmaf(z1, sc1, f1));
                    *(__half2*)&W_sh[lb * 72 + cc] = __floats2half2_rn(wv.x, wv.y);
                }
            }
            __syncthreads();
        } else if (LAST) {
            // apply bn_{NP-1} + project onto e1w
            float pa = 0.f, pb = 0.f;
#pragma unroll
            for (int nt = 0; nt < 4; nt++) {
                int cc = ncol0 + nt * 8 + 2 * tig;
                float zk0 = zc_sh[l][cc], zk1 = zc_sh[l][cc + 1];
                float sc0 = s_sh[l][cc], sc1 = s_sh[l][cc + 1];
                float f0 = sf_sh[l][cc], f1 = sf_sh[l][cc + 1];
                if (va) {
                    float2 wv = __half22float2(*(__half2*)&W_sh[la * 72 + cc]);
                    float wn0 = wv.x + lrelu(fmaf(cf[nt][0] + zk0 + x4a[nt].x, sc0, f0));
                    float wn1 = wv.y + lrelu(fmaf(cf[nt][1] + zk1 + x4a[nt].y, sc1, f1));
                    pa += wn0 * e1w_sh[cc] + wn1 * e1w_sh[cc + 1];
                }
                if (vb) {
                    float2 wv = __half22float2(*(__half2*)&W_sh[lb * 72 + cc]);
                    float wn0 = wv.x + lrelu(fmaf(cf[nt][2] + zk0 + x4b[nt].x, sc0, f0));
                    float wn1 = wv.y + lrelu(fmaf(cf[nt][3] + zk1 + x4b[nt].y, sc1, f1));
                    pb += wn0 * e1w_sh[cc] + wn1 * e1w_sh[cc + 1];
                }
            }
            pa += __shfl_xor_sync(0xffffffffu, pa, 1);
            pa += __shfl_xor_sync(0xffffffffu, pa, 2);
            pb += __shfl_xor_sync(0xffffffffu, pb, 1);
            pb += __shfl_xor_sync(0xffffffffu, pb, 2);
            int nh = wp >> 2;
            if (tig == 0) { sred[la * 2 + nh] = pa; sred[lb * 2 + nh] = pb; }
            __syncthreads();
            if (t < 64) {
                int m = m0 + t;
                if (m < M_) {
                    int dst = m + (m >= n);
                    out[(size_t)bn * N_ + dst] = sred[t * 2] + sred[t * 2 + 1] + __ldg(&e1b[0]);
                }
            }
        } else {
            // STATS (+POOLED) on z_{NP-1}
            float es0[4], es1[4], eq0[4], eq1[4], pm0[4], pm1[4];
#pragma unroll
            for (int nt = 0; nt < 4; nt++) {
                int cc = ncol0 + nt * 8 + 2 * tig;
                float zk0 = zc_sh[l][cc], zk1 = zc_sh[l][cc + 1];
                float s0 = 0.f, s1 = 0.f, q0 = 0.f, q1 = 0.f;
                float p0 = -CUDART_INF_F, p1 = -CUDART_INF_F;
                if (va) {
                    float z0 = cf[nt][0] + zk0 + x4a[nt].x;
                    float z1 = cf[nt][1] + zk1 + x4a[nt].y;
                    s0 += z0; q0 = fmaf(z0, z0, q0);
                    s1 += z1; q1 = fmaf(z1, z1, q1);
                    if (POOLED) {
                        float2 wv = __half22float2(*(__half2*)&W_sh[la * 72 + cc]);
                        p0 = x2a[nt].x / (1.f + __expf(-wv.x));
                        p1 = x2a[nt].y / (1.f + __expf(-wv.y));
                    }
                }
                if (vb) {
                    float z0 = cf[nt][2] + zk0 + x4b[nt].x;
                    float z1 = cf[nt][3] + zk1 + x4b[nt].y;
                    s0 += z0; q0 = fmaf(z0, z0, q0);
                    s1 += z1; q1 = fmaf(z1, z1, q1);
                    if (POOLED) {
                        float2 wv = __half22float2(*(__half2*)&W_sh[lb * 72 + cc]);
                        p0 = fmaxf(p0, x2b[nt].x / (1.f + __expf(-wv.x)));
                        p1 = fmaxf(p1, x2b[nt].y / (1.f + __expf(-wv.y)));
                    }
                }
                es0[nt] = s0; es1[nt] = s1; eq0[nt] = q0; eq1[nt] = q1;
                pm0[nt] = p0; pm1[nt] = p1;
            }
#pragma unroll
            for (int off = 4; off <= 16; off <<= 1) {
#pragma unroll
                for (int nt = 0; nt < 4; nt++) {
                    es0[nt] += __shfl_xor_sync(0xffffffffu, es0[nt], off);
                    es1[nt] += __shfl_xor_sync(0xffffffffu, es1[nt], off);
                    eq0[nt] += __shfl_xor_sync(0xffffffffu, eq0[nt], off);
                    eq1[nt] += __shfl_xor_sync(0xffffffffu, eq1[nt], off);
                    if (POOLED) {
                        pm0[nt] = fmaxf(pm0[nt], __shfl_xor_sync(0xffffffffu, pm0[nt], off));
                        pm1[nt] = fmaxf(pm1[nt], __shfl_xor_sync(0xffffffffu, pm1[nt], off));
                    }
                }
            }
            if (grp == 0) {
#pragma unroll
                for (int nt = 0; nt < 4; nt++) {
                    int cc = ncol0 + nt * 8 + 2 * tig;
                    atomicAdd(&ssum[cc], es0[nt]);  atomicAdd(&ssum[cc + 1], es1[nt]);
                    atomicAdd(&ssq[cc], eq0[nt]);   atomicAdd(&ssq[cc + 1], eq1[nt]);
                    if (POOLED) {
                        atomicMax(&pool_sh[cc], enc_f(pm0[nt]));
                        atomicMax(&pool_sh[cc + 1], enc_f(pm1[nt]));
                    }
                }
            }
            __syncthreads();
            if (t < 64) {
                atomicAdd(&g_estats[t], (double)ssum[t]);
                atomicAdd(&g_estats[U_ + t], (double)ssq[t]);
                if (POOLED) atomicMax(&g_pooled_u[bn * U_ + t], pool_sh[t]);
            }
        }
    }
}

// ---------------------------------------------------------------------------
// Node kernel: 200 blocks x 16 bn each. h update + x1..x4 GEMVs (fp32).
// ---------------------------------------------------------------------------
__global__ void __launch_bounds__(256) k_node(
    const float* __restrict__ x, const float* __restrict__ l0w, const float* __restrict__ l0b,
    int first, int prevL, int outL, int initPool,
    const float* __restrict__ w1, const float* __restrict__ b1,
    const float* __restrict__ w2, const float* __restrict__ b2,
    const float* __restrict__ w3, const float* __restrict__ b3,
    const float* __restrict__ w4, const float* __restrict__ b4)
{
    __shared__ float hsh[U_];
    int t = threadIdx.x;
    int mat = t >> 6, col = t & 63;
    const float* W; const float* bb;
    switch (mat) {
        case 0:  W = w1; bb = b1; break;
        case 1:  W = w2; bb = b2; break;
        case 2:  W = w3; bb = b3; break;
        default: W = w4; bb = b4; break;
    }
    float bias = __ldg(&bb[col]);
    for (int i = 0; i < 16; i++) {
        int bn = blockIdx.x * 16 + i;
        if (t < U_) {
            float hv;
            if (first) {
                hv = lrelu(x[bn * 2] * __ldg(&l0w[t]) + x[bn * 2 + 1] * __ldg(&l0w[U_ + t]) + __ldg(&l0b[t]));
            } else {
                float zh = g_x[prevL][0][bn * U_ + t] + dec_f(g_pooled_u[bn * U_ + t]);
                hv = g_h[bn * U_ + t] + lrelu(fmaf(zh, g_hcoef[t], g_hcoef[U_ + t]));
            }
            hsh[t] = hv;
            g_h[bn * U_ + t] = hv;
            if (initPool) g_pooled_u[bn * U_ + t] = 0u;
        }
        __syncthreads();
        float acc = bias;
#pragma unroll
        for (int k = 0; k < U_; k++) acc = fmaf(hsh[k], __ldg(&W[k * U_ + col]), acc);
        g_x[outL][mat][bn * U_ + col] = acc;
        __syncthreads();
    }
}

// h BN stats: one block per u (writes, not accumulates).
__global__ void __launch_bounds__(256) k_hstats(int l) {
    __shared__ float rs[256], rq[256];
    int u = blockIdx.x, t = threadIdx.x;
    float s = 0.f, q = 0.f;
    for (int i = t; i < BN_; i += 256) {
        float v = g_x[l][0][i * U_ + u] + dec_f(g_pooled_u[i * U_ + u]);
        s += v; q = fmaf(v, v, q);
    }
    rs[t] = s; rq[t] = q;
    __syncthreads();
    for (int off = 128; off >= 1; off >>= 1) {
        if (t < off) { rs[t] += rs[t + off]; rq[t] += rq[t + off]; }
        __syncthreads();
    }
    if (t == 0) { g_hstats[u] = (double)rs[0]; g_hstats[U_ + u] = (double)rq[0]; }
}

__global__ void k_finalize(int l,
                           const float* __restrict__ hg, const float* __restrict__ hb,
                           const float* __restrict__ eg, const float* __restrict__ eb) {
    int u = threadIdx.x;  // 64
    double ecnt = (double)E_;
    float emean = (float)(g_estats[u] / ecnt);
    float evar  = (float)(g_estats[U_ + u] / ecnt) - emean * emean;
    float es = eg[u] * rsqrtf(evar + EPS_);
    g_ecoef[l][0][u] = es;
    g_ecoef[l][1][u] = eb[u] - emean * es;

    double hcnt = (double)BN_;
    float hmean = (float)(g_hstats[u] / hcnt);
    float hvar  = (float)(g_hstats[U_ + u] / hcnt) - hmean * hmean;
    float hs = hg[u] * rsqrtf(hvar + EPS_);
    g_hcoef[u] = hs;
    g_hcoef[U_ + u] = hb[u] - hmean * hs;

    g_estats[u] = 0.0; g_estats[U_ + u] = 0.0;
}

__global__ void k_zdiag(float* __restrict__ out) {
    int idx = blockIdx.x * 256 + threadIdx.x;
    if (idx >= BN_) return;
    out[(size_t)idx * N_ + (idx % N_)] = 0.f;
}

extern "C" void kernel_launch(void* const* d_in, const int* in_sizes, int n_in,
                              void* d_out, int out_size) {
    const float* x    = (const float*)d_in[0];
    const float* adj  = (const float*)d_in[1];
    const float* vl0w = (const float*)d_in[2];
    const float* vl0b = (const float*)d_in[3];
    const float* vw1  = (const float*)d_in[4];
    const float* vb1  = (const float*)d_in[5];
    const float* vw2  = (const float*)d_in[6];
    const float* vb2  = (const float*)d_in[7];
    const float* vw3  = (const float*)d_in[8];
    const float* vb3  = (const float*)d_in[9];
    const float* vw4  = (const float*)d_in[10];
    const float* vb4  = (const float*)d_in[11];
    const float* vbng = (const float*)d_in[12];
    const float* vbnb = (const float*)d_in[13];
    const float* el0w = (const float*)d_in[14];
    const float* el0b = (const float*)d_in[15];
    const float* ew   = (const float*)d_in[16];
    const float* eb   = (const float*)d_in[17];
    const float* ebng = (const float*)d_in[18];
    const float* ebnb = (const float*)d_in[19];
    const float* e1w  = (const float*)d_in[20];
    const float* e1b  = (const float*)d_in[21];
    float* out = (float*)d_out;

    auto S0 = k_edge<1, true,  true,  false>;
    auto F1 = k_edge<2, true,  true,  false>;
    auto F2 = k_edge<3, false, true,  false>;
    auto AL = k_edge<3, false, false, true>;
    const int G = BN_ * 4;

    // layer 0
    k_node<<<200, 256>>>(x, vl0w, vl0b, 1, 0, 0, 1,
                         vw1, vb1, vw2, vb2, vw3, vb3, vw4, vb4);
    S0<<<G, 256>>>(adj, el0w, el0b, ew, eb, nullptr, nullptr, nullptr);
    k_hstats<<<64, 256>>>(0);
    k_finalize<<<1, 64>>>(0, vbng, vbnb, ebng, ebnb);

    // layer 1
    k_node<<<200, 256>>>(x, vl0w, vl0b, 0, 0, 1, 1,
                         vw1 + 4096, vb1 + 64, vw2 + 4096, vb2 + 64,
                         vw3 + 4096, vb3 + 64, vw4 + 4096, vb4 + 64);
    F1<<<G, 256>>>(adj, el0w, el0b, ew, eb, nullptr, nullptr, nullptr);
    k_hstats<<<64, 256>>>(1);
    k_finalize<<<1, 64>>>(1, vbng + 64, vbnb + 64, ebng + 64, ebnb + 64);

    // layer 2
    k_node<<<200, 256>>>(x, vl0w, vl0b, 0, 1, 2, 0,
                         vw1 + 8192, vb1 + 128, vw2 + 8192, vb2 + 128,
                         vw3 + 8192, vb3 + 128, vw4 + 8192, vb4 + 128);
    F2<<<G, 256>>>(adj, el0w, el0b, ew, eb, nullptr, nullptr, nullptr);
    k_finalize<<<1, 64>>>(2, vbng + 128, vbnb + 128, ebng + 128, ebnb + 128);

    // final: replay chain, apply bn2, project
    AL<<<G, 256>>>(adj, el0w, el0b, ew, eb, e1w, e1b, out);
    k_zdiag<<<(BN_ + 255) / 256, 256>>>(out);
}

// round 7
// speedup vs baseline: 2.9031x; 2.9031x over previous
#include <cuda_runtime.h>
#include <math_constants.h>
#include <cstdint>

// ---------------------------------------------------------------------------
// DIMES dense encoder, B=16, N=200, U=64, L=3
// R2 architecture + pipelined tiles + fragment-direct epilogues.
// ---------------------------------------------------------------------------

constexpr int B_ = 16, N_ = 200, M_ = 199, U_ = 64;
constexpr int BN_ = B_ * N_;                     // 3200
constexpr long long E_ = (long long)BN_ * M_;    // 636800 edge rows
constexpr float EPS_ = 1e-5f;

__device__ __align__(16) float g_w[(size_t)636800 * 64];
__device__ __align__(16) float g_z[(size_t)636800 * 64];
__device__ __align__(16) float g_h[BN_ * U_];
__device__ __align__(16) float g_x1[BN_ * U_];
__device__ __align__(16) float g_x2[BN_ * U_];
__device__ __align__(16) float g_x3[BN_ * U_];
__device__ __align__(16) float g_x4[BN_ * U_];
__device__ __align__(16) float g_pooled[BN_ * U_];
__device__ double g_estats[2 * U_];
__device__ double g_hstats[2 * U_];
__device__ __align__(16) float g_ecoef[2 * U_];  // scale, shift
__device__ __align__(16) float g_hcoef[2 * U_];

__device__ __forceinline__ float lrelu(float v) { return v >= 0.f ? v : 0.01f * v; }

// order-preserving float<->uint for atomicMax (0u below any encoded real)
__device__ __forceinline__ unsigned enc_f(float f) {
    unsigned u = __float_as_uint(f);
    return u ^ ((u & 0x80000000u) ? 0xffffffffu : 0x80000000u);
}
__device__ __forceinline__ float dec_f(unsigned k) {
    return __uint_as_float((k & 0x80000000u) ? (k ^ 0x80000000u) : ~k);
}

__device__ __forceinline__ unsigned to_tf32(float f) {
    unsigned r;
    asm("cvt.rna.tf32.f32 %0, %1;" : "=r"(r) : "f"(f));
    return r;
}

__device__ __forceinline__ void mma_tf32(float c[4], unsigned a0, unsigned a1,
                                         unsigned a2, unsigned a3,
                                         unsigned b0, unsigned b1) {
    asm volatile(
        "mma.sync.aligned.m16n8k8.row.col.f32.tf32.tf32.f32 "
        "{%0,%1,%2,%3}, {%4,%5,%6,%7}, {%8,%9}, {%0,%1,%2,%3};"
        : "+f"(c[0]), "+f"(c[1]), "+f"(c[2]), "+f"(c[3])
        : "r"(a0), "r"(a1), "r"(a2), "r"(a3), "r"(b0), "r"(b1));
}

__device__ __forceinline__ void cp_async16(unsigned dst, const void* src) {
    asm volatile("cp.async.cg.shared.global [%0], [%1], 16;" :: "r"(dst), "l"(src));
}
__device__ __forceinline__ void cp_commit() { asm volatile("cp.async.commit_group;"); }
template<int K> __device__ __forceinline__ void cp_wait() {
    asm volatile("cp.async.wait_group %0;" :: "n"(K));
}

// C(64x64) = W(fp32 smem stride 68, cvt on load) @ E(tf32 smem [k][u] stride 72)
__device__ __forceinline__ void do_gemm(const float* __restrict__ W,
                                        const float* __restrict__ Em,
                                        float cf[4][4], int la, int ncol0, int tig) {
    const int grp = (threadIdx.x & 31) >> 2;
#pragma unroll
    for (int nt = 0; nt < 4; nt++) { cf[nt][0]=0.f; cf[nt][1]=0.f; cf[nt][2]=0.f; cf[nt][3]=0.f; }
#pragma unroll
    for (int k0 = 0; k0 < 64; k0 += 8) {
        unsigned a0 = to_tf32(W[la * 68 + k0 + tig]);
        unsigned a1 = to_tf32(W[(la + 8) * 68 + k0 + tig]);
        unsigned a2 = to_tf32(W[la * 68 + k0 + tig + 4]);
        unsigned a3 = to_tf32(W[(la + 8) * 68 + k0 + tig + 4]);
#pragma unroll
        for (int nt = 0; nt < 4; nt++) {
            int col = ncol0 + nt * 8 + grp;
            unsigned b0 = __float_as_uint(Em[(k0 + tig) * 72 + col]);
            unsigned b1 = __float_as_uint(Em[(k0 + tig + 4) * 72 + col]);
            mma_tf32(cf[nt], a0, a1, a2, a3, b0, b1);
        }
    }
}

// ---------------------------------------------------------------------------
// pass1: one block per bn, 4 pipelined 64-row tiles.
//   z = w @ Ew + Eb + x3 + x4[dst]  -> g_z ; BN edge stats
//   POOLED: pooled = max_m sigmoid(w)*x2[dst] -> g_pooled ; h BN stats
//   INIT:   w built in-smem from adj and written to g_w (no loads)
// ---------------------------------------------------------------------------
template<bool INIT, bool POOLED>
__global__ void __launch_bounds__(256) k_pass1(
    const float* __restrict__ adj, const float* __restrict__ ew0, const float* __restrict__ eb0,
    const float* __restrict__ Ew,  const float* __restrict__ Eb)
{
    __shared__ float w_buf[2][64 * 68];
    __shared__ float e_sh[64 * 72];
    __shared__ float zc_sh[64];
    __shared__ float ssum[64], ssq[64];
    __shared__ unsigned pool_sh[64];
    __shared__ float adj_sh[200];

    const int bn = blockIdx.x;
    const int n = bn % N_, b = bn / N_;
    const int t = threadIdx.x;
    const int c = t & 15, r = t >> 4, c4 = c * 4;
    const int lane = t & 31, wp = t >> 5, grp = lane >> 2, tig = lane & 3;
    const int la = (wp & 3) * 16 + grp;
    const int lb = la + 8;
    const int ncol0 = (wp >> 2) * 32;

    float* wbase = g_w + (size_t)bn * M_ * U_;
    float* zbase = g_z + (size_t)bn * M_ * U_;
    const float* x2b = &g_x2[(size_t)b * N_ * U_];
    const float* x4b = &g_x4[(size_t)b * N_ * U_];

    if (t < 64) {
        zc_sh[t] = __ldg(&Eb[t]) + g_x3[bn * U_ + t];
        ssum[t] = 0.f; ssq[t] = 0.f;
        if (POOLED) pool_sh[t] = 0u;
    }
    if (INIT) {
        for (int i = t; i < M_; i += 256) {
            int dst = i + (i >= n);
            adj_sh[i] = __ldg(&adj[(size_t)bn * N_ + dst]);
        }
    }
    // E -> smem (tf32)
    for (int idx = t; idx < 1024; idx += 256) {
        int k = idx >> 4, q = (idx & 15) * 4;
        float4 v = __ldg((const float4*)&Ew[k * 64 + q]);
        v.x = __uint_as_float(to_tf32(v.x)); v.y = __uint_as_float(to_tf32(v.y));
        v.z = __uint_as_float(to_tf32(v.z)); v.w = __uint_as_float(to_tf32(v.w));
        *(float4*)&e_sh[k * 72 + q] = v;
    }

    float4 ew04, eb04;
    if (INIT) {
        ew04 = __ldg((const float4*)&ew0[c4]);
        eb04 = __ldg((const float4*)&eb0[c4]);
    } else {
        // prologue: prefetch tile 0
#pragma unroll
        for (int k = 0; k < 4; k++) {
            int idx = t + k * 256, rr = idx >> 4, q = (idx & 15) * 4;
            if (rr < M_)
                cp_async16((unsigned)__cvta_generic_to_shared(&w_buf[0][rr * 68 + q]),
                           &wbase[(size_t)rr * U_ + q]);
            else
                *(float4*)&w_buf[0][rr * 68 + q] = make_float4(0.f, 0.f, 0.f, 0.f);
        }
        cp_commit();
    }
    __syncthreads();

    // per-fragment accumulators (across tiles)
    float es0[4] = {0,0,0,0}, es1[4] = {0,0,0,0};
    float eq0[4] = {0,0,0,0}, eq1[4] = {0,0,0,0};
    float pm0[4], pm1[4];
#pragma unroll
    for (int nt = 0; nt < 4; nt++) { pm0[nt] = -CUDART_INF_F; pm1[nt] = -CUDART_INF_F; }

#pragma unroll 1
    for (int tile = 0; tile < 4; tile++) {
        const int m0 = tile * 64;
        float* W = w_buf[tile & 1];
        const int m_a = m0 + la, m_b = m0 + lb;
        const bool va = m_a < M_, vb = m_b < M_;
        const int dst_a = m_a + (m_a >= n), dst_b = m_b + (m_b >= n);

        // prefetch gathers into registers (overlap with wait + GEMM)
        float2 x4a[4], x4b_[4], x2a[4], x2b_[4];
#pragma unroll
        for (int nt = 0; nt < 4; nt++) {
            int cc = ncol0 + nt * 8 + 2 * tig;
            x4a[nt]  = va ? __ldg((const float2*)&x4b[dst_a * U_ + cc]) : make_float2(0.f, 0.f);
            x4b_[nt] = vb ? __ldg((const float2*)&x4b[dst_b * U_ + cc]) : make_float2(0.f, 0.f);
            if (POOLED) {
                x2a[nt]  = va ? __ldg((const float2*)&x2b[dst_a * U_ + cc]) : make_float2(0.f, 0.f);
                x2b_[nt] = vb ? __ldg((const float2*)&x2b[dst_b * U_ + cc]) : make_float2(0.f, 0.f);
            }
        }

        if (INIT) {
            // build w0 tile, write to global
#pragma unroll
            for (int j = 0; j < 4; j++) {
                int rr = 4 * r + j, m = m0 + rr;
                float a = (m < M_) ? adj_sh[m] : 0.f;
                float4 w4;
                w4.x = lrelu(fmaf(a, ew04.x, eb04.x));
                w4.y = lrelu(fmaf(a, ew04.y, eb04.y));
                w4.z = lrelu(fmaf(a, ew04.z, eb04.z));
                w4.w = lrelu(fmaf(a, ew04.w, eb04.w));
                if (m >= M_) w4 = make_float4(0.f, 0.f, 0.f, 0.f);
                *(float4*)&W[rr * 68 + c4] = w4;
                if (m < M_) *(float4*)&wbase[(size_t)m * U_ + c4] = w4;
            }
            __syncthreads();
        } else {
            if (tile < 3) {
                float* Wn = w_buf[(tile + 1) & 1];
                int m0n = m0 + 64;
#pragma unroll
                for (int k = 0; k < 4; k++) {
                    int idx = t + k * 256, rr = idx >> 4, q = (idx & 15) * 4;
                    if (m0n + rr < M_)
                        cp_async16((unsigned)__cvta_generic_to_shared(&Wn[rr * 68 + q]),
                                   &wbase[(size_t)(m0n + rr) * U_ + q]);
                    else if (tile == 2)
                        *(float4*)&Wn[rr * 68 + q] = make_float4(0.f, 0.f, 0.f, 0.f);
                }
                cp_commit();
                cp_wait<1>();
            } else {
                cp_wait<0>();
            }
            __syncthreads();
        }

        // GEMM
        float cf[4][4];
        do_gemm(W, e_sh, cf, la, ncol0, tig);

        // fragment-direct epilogue: z write + stats + pooled
#pragma unroll
        for (int nt = 0; nt < 4; nt++) {
            int cc = ncol0 + nt * 8 + 2 * tig;
            float zk0 = zc_sh[cc], zk1 = zc_sh[cc + 1];
            if (va) {
                float z0 = cf[nt][0] + zk0 + x4a[nt].x;
                float z1 = cf[nt][1] + zk1 + x4a[nt].y;
                *(float2*)&zbase[(size_t)m_a * U_ + cc] = make_float2(z0, z1);
                es0[nt] += z0; eq0[nt] = fmaf(z0, z0, eq0[nt]);
                es1[nt] += z1; eq1[nt] = fmaf(z1, z1, eq1[nt]);
                if (POOLED) {
                    float2 wv = *(const float2*)&W[la * 68 + cc];
                    pm0[nt] = fmaxf(pm0[nt], x2a[nt].x / (1.f + __expf(-wv.x)));
                    pm1[nt] = fmaxf(pm1[nt], x2a[nt].y / (1.f + __expf(-wv.y)));
                }
            }
            if (vb) {
                float z0 = cf[nt][2] + zk0 + x4b_[nt].x;
                float z1 = cf[nt][3] + zk1 + x4b_[nt].y;
                *(float2*)&zbase[(size_t)m_b * U_ + cc] = make_float2(z0, z1);
                es0[nt] += z0; eq0[nt] = fmaf(z0, z0, eq0[nt]);
                es1[nt] += z1; eq1[nt] = fmaf(z1, z1, eq1[nt]);
                if (POOLED) {
                    float2 wv = *(const float2*)&W[lb * 68 + cc];
                    pm0[nt] = fmaxf(pm0[nt], x2b_[nt].x / (1.f + __expf(-wv.x)));
                    pm1[nt] = fmaxf(pm1[nt], x2b_[nt].y / (1.f + __expf(-wv.y)));
                }
            }
        }
        __syncthreads();   // buffer reuse guard
    }

    // reduce across rows within warp (lanes differing in grp share columns)
#pragma unroll
    for (int off = 4; off <= 16; off <<= 1) {
#pragma unroll
        for (int nt = 0; nt < 4; nt++) {
            es0[nt] += __shfl_xor_sync(0xffffffffu, es0[nt], off);
            es1[nt] += __shfl_xor_sync(0xffffffffu, es1[nt], off);
            eq0[nt] += __shfl_xor_sync(0xffffffffu, eq0[nt], off);
            eq1[nt] += __shfl_xor_sync(0xffffffffu, eq1[nt], off);
            if (POOLED) {
                pm0[nt] = fmaxf(pm0[nt], __shfl_xor_sync(0xffffffffu, pm0[nt], off));
                pm1[nt] = fmaxf(pm1[nt], __shfl_xor_sync(0xffffffffu, pm1[nt], off));
            }
        }
    }
    if (grp == 0) {
#pragma unroll
        for (int nt = 0; nt < 4; nt++) {
            int cc = ncol0 + nt * 8 + 2 * tig;
            atomicAdd(&ssum[cc], es0[nt]);  atomicAdd(&ssum[cc + 1], es1[nt]);
            atomicAdd(&ssq[cc], eq0[nt]);   atomicAdd(&ssq[cc + 1], eq1[nt]);
            if (POOLED) {
                atomicMax(&pool_sh[cc], enc_f(pm0[nt]));
                atomicMax(&pool_sh[cc + 1], enc_f(pm1[nt]));
            }
        }
    }
    __syncthreads();
    if (t < 64) {
        atomicAdd(&g_estats[t], (double)ssum[t]);
        atomicAdd(&g_estats[U_ + t], (double)ssq[t]);
        if (POOLED) {
            float pv = dec_f(pool_sh[t]);
            g_pooled[bn * U_ + t] = pv;
            float zh = g_x1[bn * U_ + t] + pv;
            atomicAdd(&g_hstats[t], (double)zh);
            atomicAdd(&g_hstats[U_ + t], (double)(zh * zh));
        }
    }
}

// w += lrelu(bn(z))   pure streaming, float4
__global__ void k_pass2() {
    size_t idx = (size_t)blockIdx.x * 256 + threadIdx.x;  // over E*16 float4s
    int u4 = (int)(idx & 15);
    float4 z = reinterpret_cast<const float4*>(g_z)[idx];
    float4 w = reinterpret_cast<float4*>(g_w)[idx];
    float4 s  = reinterpret_cast<const float4*>(g_ecoef)[u4];
    float4 sh = reinterpret_cast<const float4*>(g_ecoef)[16 + u4];
    w.x += lrelu(fmaf(z.x, s.x, sh.x));
    w.y += lrelu(fmaf(z.y, s.y, sh.y));
    w.z += lrelu(fmaf(z.z, s.z, sh.z));
    w.w += lrelu(fmaf(z.w, s.w, sh.w));
    reinterpret_cast<float4*>(g_w)[idx] = w;
}

// last layer: residual apply fused with projection onto e1w
__global__ void __launch_bounds__(256) k_pass2_last(const float* __restrict__ e1w,
                                                    const float* __restrict__ e1b,
                                                    float* __restrict__ out) {
    __shared__ float sred[4][2];
    int t = threadIdx.x, u = t & 63, g = t >> 6;
    size_t e = (size_t)blockIdx.x * 4 + g;
    size_t o = e * U_ + u;
    float z = g_z[o], w = g_w[o];
    float wn = w + lrelu(fmaf(z, g_ecoef[u], g_ecoef[U_ + u]));
    float v = wn * __ldg(&e1w[u]);
#pragma unroll
    for (int off = 16; off; off >>= 1) v += __shfl_down_sync(0xffffffffu, v, off);
    int warp = t >> 5, lane = t & 31;
    if (lane == 0) sred[warp >> 1][warp & 1] = v;
    __syncthreads();
    if (u == 0) {
        float tot = sred[g][0] + sred[g][1] + __ldg(&e1b[0]);
        int ei = (int)e;
        int b = ei / (N_ * M_);
        int rem = ei - b * (N_ * M_);
        int n = rem / M_;
        int m = rem - n * M_;
        int dst = m + (m >= n);
        out[((size_t)(b * N_ + n)) * N_ + dst] = tot;
    }
}

// node path: h init/update + x1..x4 GEMVs. 200 blocks x 16 bn.
__global__ void __launch_bounds__(256) k_node(
    const float* __restrict__ x, const float* __restrict__ l0w, const float* __restrict__ l0b,
    int first,
    const float* __restrict__ w1, const float* __restrict__ b1,
    const float* __restrict__ w2, const float* __restrict__ b2,
    const float* __restrict__ w3, const float* __restrict__ b3,
    const float* __restrict__ w4, const float* __restrict__ b4)
{
    __shared__ float hsh[U_];
    int t = threadIdx.x;
    int mat = t >> 6, col = t & 63;
    const float* W; const float* bb; float* xout;
    switch (mat) {
        case 0:  W = w1; bb = b1; xout = g_x1; break;
        case 1:  W = w2; bb = b2; xout = g_x2; break;
        case 2:  W = w3; bb = b3; xout = g_x3; break;
        default: W = w4; bb = b4; xout = g_x4; break;
    }
    float bias = __ldg(&bb[col]);
    for (int i = 0; i < 16; i++) {
        int bn = blockIdx.x * 16 + i;
        if (t < U_) {
            float hv;
            if (first) {
                hv = lrelu(x[bn * 2] * __ldg(&l0w[t]) + x[bn * 2 + 1] * __ldg(&l0w[U_ + t]) + __ldg(&l0b[t]));
            } else {
                float zh = g_x1[bn * U_ + t] + g_pooled[bn * U_ + t];
                hv = g_h[bn * U_ + t] + lrelu(fmaf(zh, g_hcoef[t], g_hcoef[U_ + t]));
            }
            hsh[t] = hv;
            g_h[bn * U_ + t] = hv;
        }
        __syncthreads();
        float acc = bias;
#pragma unroll
        for (int k = 0; k < U_; k++) acc = fmaf(hsh[k], __ldg(&W[k * U_ + col]), acc);
        xout[bn * U_ + col] = acc;
        __syncthreads();
    }
}

__global__ void k_finalize(const float* __restrict__ hg, const float* __restrict__ hb,
                           const float* __restrict__ eg, const float* __restrict__ eb) {
    int u = threadIdx.x;  // 64
    double ecnt = (double)E_;
    float emean = (float)(g_estats[u] / ecnt);
    float evar  = (float)(g_estats[U_ + u] / ecnt) - emean * emean;
    float es = eg[u] * rsqrtf(evar + EPS_);
    g_ecoef[u] = es;
    g_ecoef[U_ + u] = eb[u] - emean * es;

    double hcnt = (double)BN_;
    float hmean = (float)(g_hstats[u] / hcnt);
    float hvar  = (float)(g_hstats[U_ + u] / hcnt) - hmean * hmean;
    float hs = hg[u] * rsqrtf(hvar + EPS_);
    g_hcoef[u] = hs;
    g_hcoef[U_ + u] = hb[u] - hmean * hs;

    g_estats[u] = 0.0; g_estats[U_ + u] = 0.0;
    g_hstats[u] = 0.0; g_hstats[U_ + u] = 0.0;
}

__global__ void k_zdiag(float* __restrict__ out) {
    int idx = blockIdx.x * 256 + threadIdx.x;
    if (idx >= BN_) return;
    out[(size_t)idx * N_ + (idx % N_)] = 0.f;
}

extern "C" void kernel_launch(void* const* d_in, const int* in_sizes, int n_in,
                              void* d_out, int out_size) {
    const float* x    = (const float*)d_in[0];
    const float* adj  = (const float*)d_in[1];
    const float* vl0w = (const float*)d_in[2];
    const float* vl0b = (const float*)d_in[3];
    const float* vw1  = (const float*)d_in[4];
    const float* vb1  = (const float*)d_in[5];
    const float* vw2  = (const float*)d_in[6];
    const float* vb2  = (const float*)d_in[7];
    const float* vw3  = (const float*)d_in[8];
    const float* vb3  = (const float*)d_in[9];
    const float* vw4  = (const float*)d_in[10];
    const float* vb4  = (const float*)d_in[11];
    const float* vbng = (const float*)d_in[12];
    const float* vbnb = (const float*)d_in[13];
    const float* el0w = (const float*)d_in[14];
    const float* el0b = (const float*)d_in[15];
    const float* ew   = (const float*)d_in[16];
    const float* eb   = (const float*)d_in[17];
    const float* ebng = (const float*)d_in[18];
    const float* ebnb = (const float*)d_in[19];
    const float* e1w  = (const float*)d_in[20];
    const float* e1b  = (const float*)d_in[21];
    float* out = (float*)d_out;

    auto S0 = k_pass1<true,  true>;    // build w0 + stats0 + pooled0
    auto F1 = k_pass1<false, true>;    // stats1 + pooled1
    auto F2 = k_pass1<false, false>;   // stats2

    // layer 0
    k_node<<<200, 256>>>(x, vl0w, vl0b, 1,
                         vw1, vb1, vw2, vb2, vw3, vb3, vw4, vb4);
    S0<<<BN_, 256>>>(adj, el0w, el0b, ew, eb);
    k_finalize<<<1, 64>>>(vbng, vbnb, ebng, ebnb);

    // layer 1
    k_node<<<200, 256>>>(x, vl0w, vl0b, 0,
                         vw1 + 4096, vb1 + 64, vw2 + 4096, vb2 + 64,
                         vw3 + 4096, vb3 + 64, vw4 + 4096, vb4 + 64);
    k_pass2<<<(int)(E_ * 16 / 256), 256>>>();
    F1<<<BN_, 256>>>(adj, el0w, el0b, ew + 4096, eb + 64);
    k_finalize<<<1, 64>>>(vbng + 64, vbnb + 64, ebng + 64, ebnb + 64);

    // layer 2
    k_node<<<200, 256>>>(x, vl0w, vl0b, 0,
                         vw1 + 8192, vb1 + 128, vw2 + 8192, vb2 + 128,
                         vw3 + 8192, vb3 + 128, vw4 + 8192, vb4 + 128);
    k_pass2<<<(int)(E_ * 16 / 256), 256>>>();
    F2<<<BN_, 256>>>(adj, el0w, el0b, ew + 8192, eb + 128);
    k_finalize<<<1, 64>>>(vbng + 128, vbnb + 128, ebng + 128, ebnb + 128);

    // final apply + projection
    k_pass2_last<<<(int)(E_ / 4), 256>>>(e1w, e1b, out);
    k_zdiag<<<(BN_ + 255) / 256, 256>>>(out);
}

// round 8
// speedup vs baseline: 3.0521x; 1.0513x over previous
#include <cuda_runtime.h>
#include <cuda_fp16.h>
#include <math_constants.h>
#include <cstdint>

// ---------------------------------------------------------------------------
// DIMES dense encoder, B=16, N=200, U=64, L=3
// pass1 per layer: [apply bn_prev from fp16 z] -> GEMM (tf32) -> z(fp16) write
//                  + BN stats + pooled. No standalone pass2.
// ---------------------------------------------------------------------------

constexpr int B_ = 16, N_ = 200, M_ = 199, U_ = 64;
constexpr int BN_ = B_ * N_;                     // 3200
constexpr long long E_ = (long long)BN_ * M_;    // 636800 edge rows
constexpr float EPS_ = 1e-5f;

__device__ __align__(16) float  g_w[(size_t)636800 * 64];
__device__ __align__(16) __half g_z16[(size_t)636800 * 64];
__device__ __align__(16) float g_h[BN_ * U_];
__device__ __align__(16) float g_x1[BN_ * U_];
__device__ __align__(16) float g_x2[BN_ * U_];
__device__ __align__(16) float g_x3[BN_ * U_];
__device__ __align__(16) float g_x4[BN_ * U_];
__device__ __align__(16) float g_pooled[BN_ * U_];
__device__ double g_estats[2 * U_];
__device__ double g_hstats[2 * U_];
__device__ __align__(16) float g_ecoef[2 * U_];  // scale, shift
__device__ __align__(16) float g_hcoef[2 * U_];

__device__ __forceinline__ float lrelu(float v) { return v >= 0.f ? v : 0.01f * v; }

__device__ __forceinline__ unsigned enc_f(float f) {
    unsigned u = __float_as_uint(f);
    return u ^ ((u & 0x80000000u) ? 0xffffffffu : 0x80000000u);
}
__device__ __forceinline__ float dec_f(unsigned k) {
    return __uint_as_float((k & 0x80000000u) ? (k ^ 0x80000000u) : ~k);
}

__device__ __forceinline__ unsigned to_tf32(float f) {
    unsigned r;
    asm("cvt.rna.tf32.f32 %0, %1;" : "=r"(r) : "f"(f));
    return r;
}

__device__ __forceinline__ void mma_tf32(float c[4], unsigned a0, unsigned a1,
                                         unsigned a2, unsigned a3,
                                         unsigned b0, unsigned b1) {
    asm volatile(
        "mma.sync.aligned.m16n8k8.row.col.f32.tf32.tf32.f32 "
        "{%0,%1,%2,%3}, {%4,%5,%6,%7}, {%8,%9}, {%0,%1,%2,%3};"
        : "+f"(c[0]), "+f"(c[1]), "+f"(c[2]), "+f"(c[3])
        : "r"(a0), "r"(a1), "r"(a2), "r"(a3), "r"(b0), "r"(b1));
}

__device__ __forceinline__ void cp_async16(unsigned dst, const void* src) {
    asm volatile("cp.async.cg.shared.global [%0], [%1], 16;" :: "r"(dst), "l"(src));
}
__device__ __forceinline__ void cp_commit() { asm volatile("cp.async.commit_group;"); }
template<int K> __device__ __forceinline__ void cp_wait() {
    asm volatile("cp.async.wait_group %0;" :: "n"(K));
}

// C(64x64) = W(fp32 smem stride 68, cvt on load) @ E(tf32 smem [k][u] stride 72)
__device__ __forceinline__ void do_gemm(const float* __restrict__ W,
                                        const float* __restrict__ Em,
                                        float cf[4][4], int la, int ncol0, int tig) {
    const int grp = (threadIdx.x & 31) >> 2;
#pragma unroll
    for (int nt = 0; nt < 4; nt++) { cf[nt][0]=0.f; cf[nt][1]=0.f; cf[nt][2]=0.f; cf[nt][3]=0.f; }
#pragma unroll
    for (int k0 = 0; k0 < 64; k0 += 8) {
        unsigned a0 = to_tf32(W[la * 68 + k0 + tig]);
        unsigned a1 = to_tf32(W[(la + 8) * 68 + k0 + tig]);
        unsigned a2 = to_tf32(W[la * 68 + k0 + tig + 4]);
        unsigned a3 = to_tf32(W[(la + 8) * 68 + k0 + tig + 4]);
#pragma unroll
        for (int nt = 0; nt < 4; nt++) {
            int col = ncol0 + nt * 8 + grp;
            unsigned b0 = __float_as_uint(Em[(k0 + tig) * 72 + col]);
            unsigned b1 = __float_as_uint(Em[(k0 + tig + 4) * 72 + col]);
            mma_tf32(cf[nt], a0, a1, a2, a3, b0, b1);
        }
    }
}

// ---------------------------------------------------------------------------
// pass1: one block per bn, 4 pipelined 64-row tiles.
//   INIT: build w0 from adj, write g_w.
//   PREV: apply bn_prev residual from fp16 z to the loaded w tile (smem+global)
//   then: GEMM -> z(fp16) write + edge BN stats (+ POOLED max & h stats)
// ---------------------------------------------------------------------------
template<bool INIT, bool PREV, bool POOLED>
__global__ void __launch_bounds__(256) k_pass1(
    const float* __restrict__ adj, const float* __restrict__ ew0, const float* __restrict__ eb0,
    const float* __restrict__ Ew,  const float* __restrict__ Eb)
{
    __shared__ float w_buf[2][64 * 68];
    __shared__ float e_sh[64 * 72];
    __shared__ float zc_sh[64];
    __shared__ float ssum[64], ssq[64];
    __shared__ unsigned pool_sh[64];
    __shared__ float adj_sh[200];

    const int bn = blockIdx.x;
    const int n = bn % N_, b = bn / N_;
    const int t = threadIdx.x;
    const int c = t & 15, r = t >> 4, c4 = c * 4;
    const int lane = t & 31, wp = t >> 5, grp = lane >> 2, tig = lane & 3;
    const int la = (wp & 3) * 16 + grp;
    const int lb = la + 8;
    const int ncol0 = (wp >> 2) * 32;

    float*  wbase = g_w   + (size_t)bn * M_ * U_;
    __half* zbase = g_z16 + (size_t)bn * M_ * U_;
    const float* x2b = &g_x2[(size_t)b * N_ * U_];
    const float* x4b = &g_x4[(size_t)b * N_ * U_];

    if (t < 64) {
        zc_sh[t] = __ldg(&Eb[t]) + g_x3[bn * U_ + t];
        ssum[t] = 0.f; ssq[t] = 0.f;
        if (POOLED) pool_sh[t] = 0u;
    }
    if (INIT) {
        for (int i = t; i < M_; i += 256) {
            int dst = i + (i >= n);
            adj_sh[i] = __ldg(&adj[(size_t)bn * N_ + dst]);
        }
    }
    // E -> smem (tf32)
    for (int idx = t; idx < 1024; idx += 256) {
        int k = idx >> 4, q = (idx & 15) * 4;
        float4 v = __ldg((const float4*)&Ew[k * 64 + q]);
        v.x = __uint_as_float(to_tf32(v.x)); v.y = __uint_as_float(to_tf32(v.y));
        v.z = __uint_as_float(to_tf32(v.z)); v.w = __uint_as_float(to_tf32(v.w));
        *(float4*)&e_sh[k * 72 + q] = v;
    }

    float4 ew04, eb04, s4, f4;
    if (INIT) {
        ew04 = __ldg((const float4*)&ew0[c4]);
        eb04 = __ldg((const float4*)&eb0[c4]);
    } else {
        if (PREV) {
            s4 = *(const float4*)&g_ecoef[c4];
            f4 = *(const float4*)&g_ecoef[U_ + c4];
        }
        // prologue: prefetch tile 0
#pragma unroll
        for (int k = 0; k < 4; k++) {
            int idx = t + k * 256, rr = idx >> 4, q = (idx & 15) * 4;
            if (rr < M_)
                cp_async16((unsigned)__cvta_generic_to_shared(&w_buf[0][rr * 68 + q]),
                           &wbase[(size_t)rr * U_ + q]);
            else
                *(float4*)&w_buf[0][rr * 68 + q] = make_float4(0.f, 0.f, 0.f, 0.f);
        }
        cp_commit();
    }
    __syncthreads();

    float es0[4] = {0,0,0,0}, es1[4] = {0,0,0,0};
    float eq0[4] = {0,0,0,0}, eq1[4] = {0,0,0,0};
    float pm0[4], pm1[4];
#pragma unroll
    for (int nt = 0; nt < 4; nt++) { pm0[nt] = -CUDART_INF_F; pm1[nt] = -CUDART_INF_F; }

#pragma unroll 1
    for (int tile = 0; tile < 4; tile++) {
        const int m0 = tile * 64;
        float* W = w_buf[tile & 1];
        const int m_a = m0 + la, m_b = m0 + lb;
        const bool va = m_a < M_, vb = m_b < M_;
        const int dst_a = m_a + (m_a >= n), dst_b = m_b + (m_b >= n);

        // prefetch gathers into registers (overlap with wait + GEMM)
        float2 x4a[4], x4b_[4], x2a[4], x2b_[4];
#pragma unroll
        for (int nt = 0; nt < 4; nt++) {
            int cc = ncol0 + nt * 8 + 2 * tig;
            x4a[nt]  = va ? __ldg((const float2*)&x4b[dst_a * U_ + cc]) : make_float2(0.f, 0.f);
            x4b_[nt] = vb ? __ldg((const float2*)&x4b[dst_b * U_ + cc]) : make_float2(0.f, 0.f);
            if (POOLED) {
                x2a[nt]  = va ? __ldg((const float2*)&x2b[dst_a * U_ + cc]) : make_float2(0.f, 0.f);
                x2b_[nt] = vb ? __ldg((const float2*)&x2b[dst_b * U_ + cc]) : make_float2(0.f, 0.f);
            }
        }

        if (INIT) {
#pragma unroll
            for (int j = 0; j < 4; j++) {
                int rr = 4 * r + j, m = m0 + rr;
                float a = (m < M_) ? adj_sh[m] : 0.f;
                float4 w4;
                w4.x = lrelu(fmaf(a, ew04.x, eb04.x));
                w4.y = lrelu(fmaf(a, ew04.y, eb04.y));
                w4.z = lrelu(fmaf(a, ew04.z, eb04.z));
                w4.w = lrelu(fmaf(a, ew04.w, eb04.w));
                if (m >= M_) w4 = make_float4(0.f, 0.f, 0.f, 0.f);
                *(float4*)&W[rr * 68 + c4] = w4;
                if (m < M_) *(float4*)&wbase[(size_t)m * U_ + c4] = w4;
            }
            __syncthreads();
        } else {
            if (tile < 3) {
                float* Wn = w_buf[(tile + 1) & 1];
                int m0n = m0 + 64;
#pragma unroll
                for (int k = 0; k < 4; k++) {
                    int idx = t + k * 256, rr = idx >> 4, q = (idx & 15) * 4;
                    if (m0n + rr < M_)
                        cp_async16((unsigned)__cvta_generic_to_shared(&Wn[rr * 68 + q]),
                                   &wbase[(size_t)(m0n + rr) * U_ + q]);
                    else if (tile == 2)
                        *(float4*)&Wn[rr * 68 + q] = make_float4(0.f, 0.f, 0.f, 0.f);
                }
                cp_commit();
                cp_wait<1>();
            } else {
                cp_wait<0>();
            }
            __syncthreads();

            if (PREV) {
                // apply bn_prev residual: w += lrelu(z_prev*s + f), z from fp16
#pragma unroll
                for (int j = 0; j < 4; j++) {
                    int rr = 4 * r + j, m = m0 + rr;
                    if (m < M_) {
                        uint2 zr = *(const uint2*)&zbase[(size_t)m * U_ + c4];
                        float2 za = __half22float2(*(__half2*)&zr.x);
                        float2 zb = __half22float2(*(__half2*)&zr.y);
                        float4 w4 = *(float4*)&W[rr * 68 + c4];
                        w4.x += lrelu(fmaf(za.x, s4.x, f4.x));
                        w4.y += lrelu(fmaf(za.y, s4.y, f4.y));
                        w4.z += lrelu(fmaf(zb.x, s4.z, f4.z));
                        w4.w += lrelu(fmaf(zb.y, s4.w, f4.w));
                        *(float4*)&W[rr * 68 + c4] = w4;
                        *(float4*)&wbase[(size_t)m * U_ + c4] = w4;
                    }
                }
                __syncthreads();
            }
        }

        // GEMM on (updated) W
        float cf[4][4];
        do_gemm(W, e_sh, cf, la, ncol0, tig);

        // fragment-direct epilogue: z(fp16) write + stats + pooled
#pragma unroll
        for (int nt = 0; nt < 4; nt++) {
            int cc = ncol0 + nt * 8 + 2 * tig;
            float zk0 = zc_sh[cc], zk1 = zc_sh[cc + 1];
            if (va) {
                float z0 = cf[nt][0] + zk0 + x4a[nt].x;
                float z1 = cf[nt][1] + zk1 + x4a[nt].y;
                *(__half2*)&zbase[(size_t)m_a * U_ + cc] = __floats2half2_rn(z0, z1);
                es0[nt] += z0; eq0[nt] = fmaf(z0, z0, eq0[nt]);
                es1[nt] += z1; eq1[nt] = fmaf(z1, z1, eq1[nt]);
                if (POOLED) {
                    float2 wv = *(const float2*)&W[la * 68 + cc];
                    pm0[nt] = fmaxf(pm0[nt], x2a[nt].x / (1.f + __expf(-wv.x)));
                    pm1[nt] = fmaxf(pm1[nt], x2a[nt].y / (1.f + __expf(-wv.y)));
                }
            }
            if (vb) {
                float z0 = cf[nt][2] + zk0 + x4b_[nt].x;
                float z1 = cf[nt][3] + zk1 + x4b_[nt].y;
                *(__half2*)&zbase[(size_t)m_b * U_ + cc] = __floats2half2_rn(z0, z1);
                es0[nt] += z0; eq0[nt] = fmaf(z0, z0, eq0[nt]);
                es1[nt] += z1; eq1[nt] = fmaf(z1, z1, eq1[nt]);
                if (POOLED) {
                    float2 wv = *(const float2*)&W[lb * 68 + cc];
                    pm0[nt] = fmaxf(pm0[nt], x2b_[nt].x / (1.f + __expf(-wv.x)));
                    pm1[nt] = fmaxf(pm1[nt], x2b_[nt].y / (1.f + __expf(-wv.y)));
                }
            }
        }
        __syncthreads();   // buffer reuse guard
    }

    // reduce across rows within warp (lanes differing in grp share columns)
#pragma unroll
    for (int off = 4; off <= 16; off <<= 1) {
#pragma unroll
        for (int nt = 0; nt < 4; nt++) {
            es0[nt] += __shfl_xor_sync(0xffffffffu, es0[nt], off);
            es1[nt] += __shfl_xor_sync(0xffffffffu, es1[nt], off);
            eq0[nt] += __shfl_xor_sync(0xffffffffu, eq0[nt], off);
            eq1[nt] += __shfl_xor_sync(0xffffffffu, eq1[nt], off);
            if (POOLED) {
                pm0[nt] = fmaxf(pm0[nt], __shfl_xor_sync(0xffffffffu, pm0[nt], off));
                pm1[nt] = fmaxf(pm1[nt], __shfl_xor_sync(0xffffffffu, pm1[nt], off));
            }
        }
    }
    if (grp == 0) {
#pragma unroll
        for (int nt = 0; nt < 4; nt++) {
            int cc = ncol0 + nt * 8 + 2 * tig;
            atomicAdd(&ssum[cc], es0[nt]);  atomicAdd(&ssum[cc + 1], es1[nt]);
            atomicAdd(&ssq[cc], eq0[nt]);   atomicAdd(&ssq[cc + 1], eq1[nt]);
            if (POOLED) {
                atomicMax(&pool_sh[cc], enc_f(pm0[nt]));
                atomicMax(&pool_sh[cc + 1], enc_f(pm1[nt]));
            }
        }
    }
    __syncthreads();
    if (t < 64) {
        atomicAdd(&g_estats[t], (double)ssum[t]);
        atomicAdd(&g_estats[U_ + t], (double)ssq[t]);
        if (POOLED) {
            float pv = dec_f(pool_sh[t]);
            g_pooled[bn * U_ + t] = pv;
            float zh = g_x1[bn * U_ + t] + pv;
            atomicAdd(&g_hstats[t], (double)zh);
            atomicAdd(&g_hstats[U_ + t], (double)(zh * zh));
        }
    }
}

// last layer: residual apply (fp16 z) fused with projection onto e1w
__global__ void __launch_bounds__(256) k_last(const float* __restrict__ e1w,
                                              const float* __restrict__ e1b,
                                              float* __restrict__ out) {
    __shared__ float sred[4][2];
    int t = threadIdx.x, u = t & 63, g = t >> 6;
    size_t e = (size_t)blockIdx.x * 4 + g;
    size_t o = e * U_ + u;
    float z = __half2float(g_z16[o]);
    float w = g_w[o];
    float wn = w + lrelu(fmaf(z, g_ecoef[u], g_ecoef[U_ + u]));
    float v = wn * __ldg(&e1w[u]);
#pragma unroll
    for (int off = 16; off; off >>= 1) v += __shfl_down_sync(0xffffffffu, v, off);
    int warp = t >> 5, lane = t & 31;
    if (lane == 0) sred[warp >> 1][warp & 1] = v;
    __syncthreads();
    if (u == 0) {
        float tot = sred[g][0] + sred[g][1] + __ldg(&e1b[0]);
        int ei = (int)e;
        int b = ei / (N_ * M_);
        int rem = ei - b * (N_ * M_);
        int n = rem / M_;
        int m = rem - n * M_;
        int dst = m + (m >= n);
        out[((size_t)(b * N_ + n)) * N_ + dst] = tot;
    }
}

// node path: h init/update + x1..x4 GEMVs. One block per bn.
__global__ void __launch_bounds__(256) k_node(
    const float* __restrict__ x, const float* __restrict__ l0w, const float* __restrict__ l0b,
    int first,
    const float* __restrict__ w1, const float* __restrict__ b1,
    const float* __restrict__ w2, const float* __restrict__ b2,
    const float* __restrict__ w3, const float* __restrict__ b3,
    const float* __restrict__ w4, const float* __restrict__ b4)
{
    __shared__ float hsh[U_];
    int bn = blockIdx.x, t = threadIdx.x;
    if (t < U_) {
        float hv;
        if (first) {
            hv = lrelu(x[bn * 2] * __ldg(&l0w[t]) + x[bn * 2 + 1] * __ldg(&l0w[U_ + t]) + __ldg(&l0b[t]));
        } else {
            float zh = g_x1[bn * U_ + t] + g_pooled[bn * U_ + t];
            hv = g_h[bn * U_ + t] + lrelu(fmaf(zh, g_hcoef[t], g_hcoef[U_ + t]));
        }
        hsh[t] = hv;
        g_h[bn * U_ + t] = hv;
    }
    __syncthreads();
    int mat = t >> 6, col = t & 63;
    const float* W; const float* bb; float* xout;
    switch (mat) {
        case 0:  W = w1; bb = b1; xout = g_x1; break;
        case 1:  W = w2; bb = b2; xout = g_x2; break;
        case 2:  W = w3; bb = b3; xout = g_x3; break;
        default: W = w4; bb = b4; xout = g_x4; break;
    }
    float acc = __ldg(&bb[col]);
#pragma unroll
    for (int k = 0; k < U_; k++) acc = fmaf(hsh[k], __ldg(&W[k * U_ + col]), acc);
    xout[bn * U_ + col] = acc;
}

__global__ void k_finalize(const float* __restrict__ hg, const float* __restrict__ hb,
                           const float* __restrict__ eg, const float* __restrict__ eb) {
    int u = threadIdx.x;  // 64
    double ecnt = (double)E_;
    float emean = (float)(g_estats[u] / ecnt);
    float evar  = (float)(g_estats[U_ + u] / ecnt) - emean * emean;
    float es = eg[u] * rsqrtf(evar + EPS_);
    g_ecoef[u] = es;
    g_ecoef[U_ + u] = eb[u] - emean * es;

    double hcnt = (double)BN_;
    float hmean = (float)(g_hstats[u] / hcnt);
    float hvar  = (float)(g_hstats[U_ + u] / hcnt) - hmean * hmean;
    float hs = hg[u] * rsqrtf(hvar + EPS_);
    g_hcoef[u] = hs;
    g_hcoef[U_ + u] = hb[u] - hmean * hs;

    g_estats[u] = 0.0; g_estats[U_ + u] = 0.0;
    g_hstats[u] = 0.0; g_hstats[U_ + u] = 0.0;
}

__global__ void k_zdiag(float* __restrict__ out) {
    int idx = blockIdx.x * 256 + threadIdx.x;
    if (idx >= BN_) return;
    out[(size_t)idx * N_ + (idx % N_)] = 0.f;
}

extern "C" void kernel_launch(void* const* d_in, const int* in_sizes, int n_in,
                              void* d_out, int out_size) {
    const float* x    = (const float*)d_in[0];
    const float* adj  = (const float*)d_in[1];
    const float* vl0w = (const float*)d_in[2];
    const float* vl0b = (const float*)d_in[3];
    const float* vw1  = (const float*)d_in[4];
    const float* vb1  = (const float*)d_in[5];
    const float* vw2  = (const float*)d_in[6];
    const float* vb2  = (const float*)d_in[7];
    const float* vw3  = (const float*)d_in[8];
    const float* vb3  = (const float*)d_in[9];
    const float* vw4  = (const float*)d_in[10];
    const float* vb4  = (const float*)d_in[11];
    const float* vbng = (const float*)d_in[12];
    const float* vbnb = (const float*)d_in[13];
    const float* el0w = (const float*)d_in[14];
    const float* el0b = (const float*)d_in[15];
    const float* ew   = (const float*)d_in[16];
    const float* eb   = (const float*)d_in[17];
    const float* ebng = (const float*)d_in[18];
    const float* ebnb = (const float*)d_in[19];
    const float* e1w  = (const float*)d_in[20];
    const float* e1b  = (const float*)d_in[21];
    float* out = (float*)d_out;

    auto S0 = k_pass1<true,  false, true >;   // build w0 + stats0 + pooled0
    auto F1 = k_pass1<false, true,  true >;   // apply bn0 + stats1 + pooled1
    auto F2 = k_pass1<false, true,  false>;   // apply bn1 + stats2

    // layer 0
    k_node<<<BN_, 256>>>(x, vl0w, vl0b, 1,
                         vw1, vb1, vw2, vb2, vw3, vb3, vw4, vb4);
    S0<<<BN_, 256>>>(adj, el0w, el0b, ew, eb);
    k_finalize<<<1, 64>>>(vbng, vbnb, ebng, ebnb);

    // layer 1
    k_node<<<BN_, 256>>>(x, vl0w, vl0b, 0,
                         vw1 + 4096, vb1 + 64, vw2 + 4096, vb2 + 64,
                         vw3 + 4096, vb3 + 64, vw4 + 4096, vb4 + 64);
    F1<<<BN_, 256>>>(adj, el0w, el0b, ew + 4096, eb + 64);
    k_finalize<<<1, 64>>>(vbng + 64, vbnb + 64, ebng + 64, ebnb + 64);

    // layer 2
    k_node<<<BN_, 256>>>(x, vl0w, vl0b, 0,
                         vw1 + 8192, vb1 + 128, vw2 + 8192, vb2 + 128,
                         vw3 + 8192, vb3 + 128, vw4 + 8192, vb4 + 128);
    F2<<<BN_, 256>>>(adj, el0w, el0b, ew + 8192, eb + 128);
    k_finalize<<<1, 64>>>(vbng + 128, vbnb + 128, ebng + 128, ebnb + 128);

    // final apply + projection
    k_last<<<(int)(E_ / 4), 256>>>(e1w, e1b, out);
    k_zdiag<<<(BN_ + 255) / 256, 256>>>(out);
}